// round 17
// baseline (speedup 1.0000x reference)
#include <cuda_runtime.h>
#include <cuda_bf16.h>
#include <math.h>
#include <stdint.h>

// ---------------- problem constants ----------------
#define BN  4
#define CIN 768
#define FC  256
#define N0  1024   // 32*32

// ---------------- scratch (device globals; no allocations allowed) ----------------
// HWC layouts: [(b*H + y)*W + x][c]
__device__ float g_x0t [BN*N0*FC];                 //  4 MB fusion out (HWC, 32x32)
__device__ float g_enht[BN*N0*FC];                 //  4 MB enhanced   (HWC, 32x32)
__device__ float g_off [BN*32*64*64];              //  2 MB offsets (NCHW, max stage-2)
__device__ __nv_bfloat16 g_uph[BN*128*128*FC];     // 33.5 MB upsampled hi (HWC bf16)
__device__ __nv_bfloat16 g_upl[BN*128*128*FC];     // 33.5 MB upsampled lo
__device__ float g_c1t [BN*64*64*FC];              // 16 MB conv1 out (HWC)
__device__ float g_c2t [BN*128*128*FC];            // 64 MB conv2 out (HWC)
// pre-split conv weights: [(kh*3+kw)*256 + n][c] bf16
__device__ __nv_bfloat16 g_w1h[9*FC*FC], g_w1l[9*FC*FC];
__device__ __nv_bfloat16 g_w2h[9*FC*FC], g_w2l[9*FC*FC];
// fusion operands (bf16 hi/lo): activations [l][b*1024+s][c], weights [l][f][c]
__device__ __nv_bfloat16 g_fah[4*BN*N0*CIN], g_fal[4*BN*N0*CIN];   // 25.2 MB each
__device__ __nv_bfloat16 g_pwh[4*FC*CIN],    g_pwl[4*FC*CIN];      // 1.6 MB each

__device__ __forceinline__ float gelu_exact(float x) {
    return 0.5f * x * (1.0f + erff(x * 0.70710678118654752440f));
}

// ---------------- warp-MMA helpers (sm_80+ path; no 'a'-gated instructions) ------
__device__ __forceinline__ uint32_t smem_u32(const void* p) {
    return (uint32_t)__cvta_generic_to_shared(p);
}
__device__ __forceinline__ void mma_bf16(float* c, const uint32_t* a, const uint32_t* b) {
    asm volatile(
        "mma.sync.aligned.m16n8k16.row.col.f32.bf16.bf16.f32 "
        "{%0,%1,%2,%3}, {%4,%5,%6,%7}, {%8,%9}, {%0,%1,%2,%3};"
        : "+f"(c[0]), "+f"(c[1]), "+f"(c[2]), "+f"(c[3])
        : "r"(a[0]), "r"(a[1]), "r"(a[2]), "r"(a[3]), "r"(b[0]), "r"(b[1]));
}
__device__ __forceinline__ void ldm_x4(uint32_t* r, uint32_t addr) {
    asm volatile("ldmatrix.sync.aligned.m8n8.x4.shared.b16 {%0,%1,%2,%3}, [%4];"
        : "=r"(r[0]), "=r"(r[1]), "=r"(r[2]), "=r"(r[3]) : "r"(addr));
}
__device__ __forceinline__ void cp16(uint32_t dst, const void* src, int sz) {
    asm volatile("cp.async.cg.shared.global [%0], [%1], 16, %2;"
        :: "r"(dst), "l"(src), "r"(sz));
}
#define CP_COMMIT() asm volatile("cp.async.commit_group;" ::: "memory")
#define CP_WAIT(N)  asm volatile("cp.async.wait_group %0;" :: "n"(N) : "memory")

// =====================================================================
// Kernel 0a: weight pre-split: OIHW fp32 -> [(kh3+kw)*256+n][c] bf16 hi/lo
// =====================================================================
__global__ __launch_bounds__(256)
void wconv_kernel(const float* __restrict__ w, __nv_bfloat16* __restrict__ oh,
                  __nv_bfloat16* __restrict__ ol) {
    int idx = blockIdx.x * 256 + threadIdx.x;  // = (j*256 + n)*256 + c
    int c = idx & 255;
    int n = (idx >> 8) & 255;
    int j = idx >> 16;
    float v = w[((n << 8) + c) * 9 + j];
    __nv_bfloat16 hi = __float2bfloat16_rn(v);
    oh[idx] = hi;
    ol[idx] = __float2bfloat16_rn(v - __bfloat162float(hi));
}

// =====================================================================
// Kernel 0b: batched transpose + bf16 hi/lo split.
// src[z][r][k] fp32 -> dh/dl[z][k][r] bf16. Tile 32x32 via padded smem.
// =====================================================================
__global__ __launch_bounds__(256)
void tsplit_kernel(const float* __restrict__ src, __nv_bfloat16* __restrict__ dh,
                   __nv_bfloat16* __restrict__ dl, int R, int K) {
    __shared__ float t[32][33];
    int k0 = blockIdx.x * 32, r0 = blockIdx.y * 32;
    size_t base = (size_t)blockIdx.z * R * K;
    int tid = threadIdx.x;
    int tx = tid & 31, ty = tid >> 5;          // ty: 8 rows per pass
    #pragma unroll
    for (int i = 0; i < 4; i++)
        t[ty + 8*i][tx] = src[base + (size_t)(r0 + ty + 8*i)*K + k0 + tx];
    __syncthreads();
    #pragma unroll
    for (int i = 0; i < 4; i++) {
        int k = ty + 8*i, r = tx;
        float v = t[tx][ty + 8*i];             // = src[r0+r][k0+k]
        __nv_bfloat16 hi = __float2bfloat16_rn(v);
        size_t o = base + (size_t)(k0 + k)*R + r0 + r;
        dh[o] = hi;
        dl[o] = __float2bfloat16_rn(v - __bfloat162float(hi));
    }
}

// =====================================================================
// Kernel 1: weighted fusion via warp-MMA bf16-split GEMM.
// Per layer l: acc = A_l (M=4096 x K=768) @ W_l^T (f-major), then
// outacc += softmax(lw)[l] * gelu(acc). CTA tile 64M x 128N, 8 warps 2x4,
// warp tile 32x32. KT=32 -> 24 chunks/layer, 96 total, double-buffered.
// =====================================================================
#define F_APS 5120                    // A plane: 64*80
#define F_BPS 10240                   // B plane: 128*80
#define F_BUF (2*F_APS + 2*F_BPS)     // 30720
#define FUS_SMEM (2*F_BUF)            // 61440

#define F_LOAD(ci, buf)                                                         \
    do {                                                                        \
        int l_ = (ci)/24, kk_ = ((ci)%24)*32;                                   \
        uint32_t tb_ = sb + (uint32_t)(buf)*F_BUF;                              \
        size_t ao_ = ((size_t)l_*4096 + m0 + ar)*CIN + kk_ + aseg*8;            \
        cp16(tb_ + ar*80 + aseg*16,         fah + ao_, 16);                     \
        cp16(tb_ + F_APS + ar*80 + aseg*16, fal + ao_, 16);                     \
        size_t bo_ = ((size_t)l_*FC + n0c + br)*CIN + kk_ + bseg*8;             \
        uint32_t bb_ = tb_ + 2*F_APS + br*80 + bseg*16;                         \
        cp16(bb_,              pwh + bo_,     16);                              \
        cp16(bb_ + 16,         pwh + bo_ + 8, 16);                              \
        cp16(bb_ + F_BPS,      pwl + bo_,     16);                              \
        cp16(bb_ + F_BPS + 16, pwl + bo_ + 8, 16);                              \
    } while (0)

__global__ __launch_bounds__(256, 2)
void fusion_mma(const __nv_bfloat16* __restrict__ fah, const __nv_bfloat16* __restrict__ fal,
                const __nv_bfloat16* __restrict__ pwh, const __nv_bfloat16* __restrict__ pwl,
                const float* __restrict__ lwr, float* __restrict__ out) {
    extern __shared__ char sm[];
    uint32_t sb = smem_u32(sm);
    int tid = threadIdx.x;
    int lane = tid & 31, wid = tid >> 5;
    int m0 = blockIdx.x * 64;
    int n0c = blockIdx.y * 128;

    // softmax over 4 layer weights
    float l0 = __ldg(lwr), l1 = __ldg(lwr+1), l2 = __ldg(lwr+2), l3 = __ldg(lwr+3);
    float mx = fmaxf(fmaxf(l0,l1), fmaxf(l2,l3));
    float e0 = expf(l0-mx), e1 = expf(l1-mx), e2 = expf(l2-mx), e3 = expf(l3-mx);
    float inv = 1.0f/(e0+e1+e2+e3);
    float lw[4] = {e0*inv, e1*inv, e2*inv, e3*inv};

    // load geometry: A 64 rows x 4 segs; B 128 rows x (2 segs per thread)
    int ar = tid >> 2, aseg = tid & 3;
    int br = tid >> 1, bseg = (tid & 1) * 2;

    // warp compute geometry: 2(M) x 4(N), warp tile 32x32
    int wm = wid >> 2;
    int wn = wid & 3;
    int alr = lane & 15;
    int alc = (lane >> 4) << 4;
    int bg = lane >> 3;
    int brow_off = ((bg >> 1) << 3) + (lane & 7);
    int bcol = (bg & 1) << 4;

    float acc[2][4][4], outacc[2][4][4];
    #pragma unroll
    for (int i=0;i<2;i++)
        #pragma unroll
        for (int j=0;j<4;j++)
            #pragma unroll
            for (int k=0;k<4;k++) { acc[i][j][k]=0.f; outacc[i][j][k]=0.f; }

    F_LOAD(0, 0);
    CP_COMMIT();

    for (int ci = 0; ci < 96; ci++) {
        int buf = ci & 1;
        if (ci < 95) {
            F_LOAD(ci+1, (ci+1)&1);
            CP_COMMIT();
            CP_WAIT(1);
        } else {
            CP_WAIT(0);
        }
        __syncthreads();

        uint32_t base = sb + (uint32_t)buf*F_BUF;
        #pragma unroll
        for (int k16 = 0; k16 < 2; k16++) {
            uint32_t ah4[2][4], al4[2][4];
            #pragma unroll
            for (int mt = 0; mt < 2; mt++) {
                uint32_t aaddr = base + (uint32_t)((wm*32 + mt*16 + alr)*80 + k16*32 + alc);
                ldm_x4(ah4[mt], aaddr);
                ldm_x4(al4[mt], aaddr + F_APS);
            }
            #pragma unroll
            for (int np = 0; np < 2; np++) {
                uint32_t baddr = base + 2*F_APS +
                    (uint32_t)((wn*32 + np*16 + brow_off)*80 + k16*32 + bcol);
                uint32_t th[4], tl[4];
                ldm_x4(th, baddr);
                ldm_x4(tl, baddr + F_BPS);
                uint32_t bh0[2] = {th[0], th[1]}, bh1[2] = {th[2], th[3]};
                uint32_t bl0[2] = {tl[0], tl[1]}, bl1[2] = {tl[2], tl[3]};
                #pragma unroll
                for (int mt = 0; mt < 2; mt++) {
                    mma_bf16(acc[mt][np*2],   ah4[mt], bh0);
                    mma_bf16(acc[mt][np*2],   ah4[mt], bl0);
                    mma_bf16(acc[mt][np*2],   al4[mt], bh0);
                    mma_bf16(acc[mt][np*2+1], ah4[mt], bh1);
                    mma_bf16(acc[mt][np*2+1], ah4[mt], bl1);
                    mma_bf16(acc[mt][np*2+1], al4[mt], bh1);
                }
            }
        }
        // layer boundary: fold gelu * lw into outacc, reset acc
        if ((ci % 24) == 23) {
            float wl = lw[ci / 24];
            #pragma unroll
            for (int mt = 0; mt < 2; mt++)
                #pragma unroll
                for (int nt = 0; nt < 4; nt++)
                    #pragma unroll
                    for (int k = 0; k < 4; k++) {
                        outacc[mt][nt][k] = fmaf(wl, gelu_exact(acc[mt][nt][k]),
                                                 outacc[mt][nt][k]);
                        acc[mt][nt][k] = 0.f;
                    }
        }
        __syncthreads();
    }

    // epilogue: HWC float2 stores (m = b*1024+s maps directly to HWC row)
    #pragma unroll
    for (int mt = 0; mt < 2; mt++) {
        int rbase = m0 + wm*32 + mt*16 + (lane >> 2);
        #pragma unroll
        for (int h2 = 0; h2 < 2; h2++) {
            int mr = rbase + h2*8;
            float* op = out + (size_t)mr*FC;
            #pragma unroll
            for (int nt = 0; nt < 4; nt++) {
                int n = n0c + wn*32 + nt*8 + (lane & 3)*2;
                float2 v;
                v.x = outacc[mt][nt][h2*2+0];
                v.y = outacc[mt][nt][h2*2+1];
                *(float2*)(op + n) = v;
            }
        }
    }
}

// =====================================================================
// Kernel 2: depthwise 3x3 + BN + residual ReLU (HWC, 32x32)
// =====================================================================
__global__ __launch_bounds__(256)
void enhance_kernel(const float* __restrict__ x, const float* __restrict__ dw,
                    const float* __restrict__ bnp, float* __restrict__ out) {
    __shared__ float dws[FC*9];
    __shared__ float bsc[FC], bsh[FC];
    int tid = threadIdx.x;
    for (int i = tid; i < FC*9; i += 256) dws[i] = dw[i];
    {
        float g = bnp[tid], be = bnp[256+tid], mu = bnp[512+tid], va = bnp[768+tid];
        float sc = g * rsqrtf(va + 1e-5f);
        bsc[tid] = sc; bsh[tid] = be - mu*sc;
    }
    __syncthreads();
    int idx = blockIdx.x * 256 + tid;          // (b*1024 + s)*256 + c
    int c = idx & 255;
    int sp = idx >> 8;
    int s = sp & 1023;
    int w = s & 31, h = s >> 5;
    float xc = x[idx];
    float y = 0.f;
    #pragma unroll
    for (int kh = 0; kh < 3; kh++) {
        int iy = h + kh - 1;
        if ((unsigned)iy < 32u) {
            #pragma unroll
            for (int kw = 0; kw < 3; kw++) {
                int ix = w + kw - 1;
                if ((unsigned)ix < 32u)
                    y = fmaf(dws[c*9 + kh*3 + kw],
                             x[((sp - s) + (iy<<5) + ix)*FC + c], y);
            }
        }
    }
    out[idx] = fmaxf(fmaf(y, bsc[c], bsh[c]) + xc, 0.f);
}

// =====================================================================
// Kernel 3: 1x1 offset conv (HWC in, 256 -> 32) + bias. Warp-per-pixel.
// =====================================================================
__global__ __launch_bounds__(256)
void offset_kernel(const float* __restrict__ in, const float* __restrict__ ow,
                   const float* __restrict__ ob, float* __restrict__ off,
                   int H, int W) {
    __shared__ float ws[FC*32];   // [c][j]
    int tid = threadIdx.x;
    for (int i = tid; i < FC*32; i += 256) {
        int c = i >> 5, j = i & 31;
        ws[i] = ow[j*FC + c];
    }
    __syncthreads();
    int HW = H*W;
    int wid = tid >> 5, j = tid & 31;
    int p = blockIdx.x * 8 + wid;              // pixel in [0, BN*HW)
    const float4* ip = (const float4*)(in + (size_t)p*FC);
    float acc = __ldg(&ob[j]);
    #pragma unroll 4
    for (int c4 = 0; c4 < 64; c4++) {
        float4 v = ip[c4];                     // uniform across warp -> broadcast
        int c = c4 * 4;
        acc = fmaf(v.x, ws[(c+0)*32 + j], acc);
        acc = fmaf(v.y, ws[(c+1)*32 + j], acc);
        acc = fmaf(v.z, ws[(c+2)*32 + j], acc);
        acc = fmaf(v.w, ws[(c+3)*32 + j], acc);
    }
    int b = p / HW, s = p - b*HW;
    off[(b*32 + j)*HW + s] = acc;
}

// =====================================================================
// Kernel 4: DySample bilinear gather, 4 channels/thread (shared offsets,
// float4 gathers, packed bf16x4 stores). HWC fp32 in, bf16 hi/lo out.
// =====================================================================
__global__ __launch_bounds__(256)
void upsample_kernel(const float* __restrict__ x, const float* __restrict__ off,
                     __nv_bfloat16* __restrict__ oh, __nv_bfloat16* __restrict__ ol,
                     int H, int W) {
    int W2 = 2*W, H2 = 2*H, HW = H*W;
    int idx = blockIdx.x*256 + threadIdx.x;   // (sp)*64 + c4grp
    int cg = idx & 63;                         // channel group: 4 ch each
    int c  = cg << 2;
    int sp = idx >> 6;
    int wo = sp % W2;
    int t  = sp / W2;
    int ho = t % H2;
    int b  = t / H2;
    int g  = c >> 6;
    int h = ho >> 1, dh = ho & 1, w = wo >> 1, dw = wo & 1;
    int obase = ((b*32 + g*4 + dh*2 + dw)*H + h)*W + w;
    float offx = off[obase]         * 0.25f + (0.5f*(float)dw - 0.25f);
    float offy = off[obase + 16*HW] * 0.25f + (0.5f*(float)dh - 0.25f);
    float px = fminf(fmaxf((float)w + offx, 0.f), (float)(W-1));
    float py = fminf(fmaxf((float)h + offy, 0.f), (float)(H-1));
    int x0 = (int)px;
    int y0 = (int)py;
    float wx = px - (float)x0, wy = py - (float)y0;
    int x1 = min(x0+1, W-1);
    int y1 = min(y0+1, H-1);
    const float* ib = x + (size_t)b*HW*FC + c;
    float4 v00 = *(const float4*)(ib + ((size_t)y0*W + x0)*FC);
    float4 v01 = *(const float4*)(ib + ((size_t)y0*W + x1)*FC);
    float4 v10 = *(const float4*)(ib + ((size_t)y1*W + x0)*FC);
    float4 v11 = *(const float4*)(ib + ((size_t)y1*W + x1)*FC);
    float vr[4];
    vr[0] = (v00.x + (v01.x-v00.x)*wx) + ((v10.x + (v11.x-v10.x)*wx) - (v00.x + (v01.x-v00.x)*wx))*wy;
    vr[1] = (v00.y + (v01.y-v00.y)*wx) + ((v10.y + (v11.y-v10.y)*wx) - (v00.y + (v01.y-v00.y)*wx))*wy;
    vr[2] = (v00.z + (v01.z-v00.z)*wx) + ((v10.z + (v11.z-v10.z)*wx) - (v00.z + (v01.z-v00.z)*wx))*wy;
    vr[3] = (v00.w + (v01.w-v00.w)*wx) + ((v10.w + (v11.w-v10.w)*wx) - (v00.w + (v01.w-v00.w)*wx))*wy;
    __nv_bfloat16 hi[4], lo[4];
    #pragma unroll
    for (int i = 0; i < 4; i++) {
        hi[i] = __float2bfloat16_rn(vr[i]);
        lo[i] = __float2bfloat16_rn(vr[i] - __bfloat162float(hi[i]));
    }
    size_t o = (size_t)sp*FC + c;
    *(uint2*)(oh + o) = *(uint2*)hi;
    *(uint2*)(ol + o) = *(uint2*)lo;
}

// =====================================================================
// Kernel 5: 3x3 conv 256->256, warp-MMA bf16-split implicit GEMM + BN + ReLU.
// CTA tile 128(M) x 128(N), KT=32 -> 72 chunks, SMEM 84KB, 2 CTAs/SM.
// =====================================================================
#define APS 10240                     // plane stride: 128*80
#define BUFSZ (4*APS)                 // 40960
#define CONV_SMEM (2048 + 2*BUFSZ)    // 83968

#define LOAD_CHUNK(ci, buf)                                                     \
    do {                                                                        \
        int tap_ = (ci) >> 3, cc_ = ((ci) & 7) << 5;                            \
        int kh_ = tap_ / 3, kw_ = tap_ - kh_*3;                                 \
        int yy_ = y + kh_ - 1, xx_ = x + kw_ - 1;                               \
        bool val_ = ((unsigned)yy_ < (unsigned)H) && ((unsigned)xx_ < (unsigned)W); \
        int vsz_ = val_ ? 16 : 0;                                               \
        long ao_ = ((long)(b*H + (val_?yy_:0))*W + (val_?xx_:0))*FC + cc_ + hseg*8; \
        uint32_t ab_ = sb + 2048u + (uint32_t)(buf)*BUFSZ + lr*80 + hseg*16;    \
        const __nv_bfloat16* ah_ = inh + ao_;                                   \
        const __nv_bfloat16* al_ = inl + ao_;                                   \
        long bo_ = ((long)(tap_*FC + n0c + lr))*FC + cc_ + hseg*8;              \
        const __nv_bfloat16* bh_ = wh + bo_;                                    \
        const __nv_bfloat16* bl_ = wl + bo_;                                    \
        _Pragma("unroll")                                                       \
        for (int j_ = 0; j_ < 2; j_++) {                                        \
            cp16(ab_ + j_*16,         ah_ + j_*8, vsz_);                        \
            cp16(ab_ + APS + j_*16,   al_ + j_*8, vsz_);                        \
            cp16(ab_ + 2*APS + j_*16, bh_ + j_*8, 16);                          \
            cp16(ab_ + 3*APS + j_*16, bl_ + j_*8, 16);                          \
        }                                                                       \
    } while (0)

__global__ __launch_bounds__(256, 2)
void conv_mma(const __nv_bfloat16* __restrict__ inh, const __nv_bfloat16* __restrict__ inl,
              const __nv_bfloat16* __restrict__ wh,  const __nv_bfloat16* __restrict__ wl,
              const float* __restrict__ bnp, float* __restrict__ out, int H, int W) {
    extern __shared__ char sm[];
    float* bsc = (float*)sm;
    float* bshf = (float*)(sm + 1024);
    uint32_t sb = smem_u32(sm);
    int tid = threadIdx.x;
    int lane = tid & 31, wid = tid >> 5;
    const int HW = H*W;
    int m0 = blockIdx.x * 128;
    int n0c = blockIdx.y * 128;

    {
        float g = bnp[tid], be = bnp[256+tid], mu = bnp[512+tid], va = bnp[768+tid];
        float sc = g * rsqrtf(va + 1e-5f);
        bsc[tid] = sc; bshf[tid] = be - mu*sc;
    }

    int lr = tid >> 1;
    int hseg = (tid & 1) * 2;
    int mrow = m0 + lr;
    int b = mrow / HW;
    int s = mrow - b*HW;
    int y = s / W, x = s - y*W;

    int wm = wid & 3;
    int wn = wid >> 2;
    int alr = lane & 15;
    int alc = (lane >> 4) << 4;
    int bg = lane >> 3;
    int brow_off = ((bg >> 1) << 3) + (lane & 7);
    int bcol = (bg & 1) << 4;

    float acc[2][8][4];
    #pragma unroll
    for (int i=0;i<2;i++)
        #pragma unroll
        for (int j=0;j<8;j++)
            #pragma unroll
            for (int k=0;k<4;k++) acc[i][j][k]=0.f;

    LOAD_CHUNK(0, 0);
    CP_COMMIT();

    for (int ci = 0; ci < 72; ci++) {
        int buf = ci & 1;
        if (ci < 71) {
            LOAD_CHUNK(ci+1, (ci+1)&1);
            CP_COMMIT();
            CP_WAIT(1);
        } else {
            CP_WAIT(0);
        }
        __syncthreads();

        uint32_t base = sb + 2048u + (uint32_t)buf*BUFSZ;
        #pragma unroll
        for (int k16 = 0; k16 < 2; k16++) {
            uint32_t ah4[2][4], al4[2][4];
            #pragma unroll
            for (int mt = 0; mt < 2; mt++) {
                uint32_t aaddr = base + (uint32_t)((wm*32 + mt*16 + alr)*80 + k16*32 + alc);
                ldm_x4(ah4[mt], aaddr);
                ldm_x4(al4[mt], aaddr + APS);
            }
            #pragma unroll
            for (int np = 0; np < 4; np++) {
                uint32_t baddr = base + 2*APS +
                    (uint32_t)((wn*64 + np*16 + brow_off)*80 + k16*32 + bcol);
                uint32_t th[4], tl[4];
                ldm_x4(th, baddr);
                ldm_x4(tl, baddr + APS);
                uint32_t bh0[2] = {th[0], th[1]}, bh1[2] = {th[2], th[3]};
                uint32_t bl0[2] = {tl[0], tl[1]}, bl1[2] = {tl[2], tl[3]};
                #pragma unroll
                for (int mt = 0; mt < 2; mt++) {
                    mma_bf16(acc[mt][np*2],   ah4[mt], bh0);
                    mma_bf16(acc[mt][np*2],   ah4[mt], bl0);
                    mma_bf16(acc[mt][np*2],   al4[mt], bh0);
                    mma_bf16(acc[mt][np*2+1], ah4[mt], bh1);
                    mma_bf16(acc[mt][np*2+1], ah4[mt], bl1);
                    mma_bf16(acc[mt][np*2+1], al4[mt], bh1);
                }
            }
        }
        __syncthreads();
    }

    #pragma unroll
    for (int mt = 0; mt < 2; mt++) {
        int rbase = m0 + wm*32 + mt*16 + (lane >> 2);
        #pragma unroll
        for (int h2 = 0; h2 < 2; h2++) {
            int mr = rbase + h2*8;
            int bb2 = mr / HW;
            int ss  = mr - bb2*HW;
            float* op = out + ((size_t)bb2*HW + ss)*FC;
            #pragma unroll
            for (int nt = 0; nt < 8; nt++) {
                int n = n0c + wn*64 + nt*8 + (lane & 3)*2;
                float2 v;
                v.x = fmaxf(fmaf(acc[mt][nt][h2*2+0], bsc[n],   bshf[n]),   0.f);
                v.y = fmaxf(fmaf(acc[mt][nt][h2*2+1], bsc[n+1], bshf[n+1]), 0.f);
                *(float2*)(op + n) = v;
            }
        }
    }
}

// =====================================================================
// Kernel 6: head conv 3x3, 256 -> 1, + bias (HWC in)
// =====================================================================
__global__ __launch_bounds__(256)
void outconv_kernel(const float* __restrict__ in, const float* __restrict__ wv,
                    const float* __restrict__ bias, float* __restrict__ out,
                    int H, int W) {
    __shared__ float ws2[9*FC];   // [j][c]
    int tid = threadIdx.x;
    for (int i = tid; i < 9*FC; i += 256) {
        int j = i >> 8, c = i & 255;
        ws2[i] = wv[c*9 + j];
    }
    __syncthreads();
    int HW = H*W;
    int idx = blockIdx.x*256 + tid;
    int s = idx % HW;
    int b = idx / HW;
    int y = s / W, x = s % W;
    float acc = __ldg(bias);
    #pragma unroll
    for (int kh = 0; kh < 3; kh++) {
        int iy = y + kh - 1;
        if ((unsigned)iy >= (unsigned)H) continue;
        #pragma unroll
        for (int kw = 0; kw < 3; kw++) {
            int ix = x + kw - 1;
            if ((unsigned)ix >= (unsigned)W) continue;
            const float4* ip = (const float4*)(in + ((size_t)(b*H + iy)*W + ix)*FC);
            const float4* wp = (const float4*)(ws2 + (kh*3 + kw)*FC);
            #pragma unroll 8
            for (int c = 0; c < 64; c++) {
                float4 a = ip[c], w4 = wp[c];
                acc = fmaf(a.x, w4.x, acc); acc = fmaf(a.y, w4.y, acc);
                acc = fmaf(a.z, w4.z, acc); acc = fmaf(a.w, w4.w, acc);
            }
        }
    }
    out[idx] = acc;
}

// =====================================================================
// launcher
// =====================================================================
extern "C" void kernel_launch(void* const* d_in, const int* in_sizes, int n_in,
                              void* d_out, int out_size) {
    const float* f1  = (const float*)d_in[0];
    const float* f2  = (const float*)d_in[1];
    const float* f3  = (const float*)d_in[2];
    const float* f4  = (const float*)d_in[3];
    const float* pw  = (const float*)d_in[4];
    const float* lw  = (const float*)d_in[5];
    const float* dww = (const float*)d_in[6];
    const float* bne = (const float*)d_in[7];
    const float* ow1 = (const float*)d_in[8];
    const float* ob1 = (const float*)d_in[9];
    const float* cw1 = (const float*)d_in[10];
    const float* bn1 = (const float*)d_in[11];
    const float* ow2 = (const float*)d_in[12];
    const float* ob2 = (const float*)d_in[13];
    const float* cw2 = (const float*)d_in[14];
    const float* bn2 = (const float*)d_in[15];
    const float* owv = (const float*)d_in[16];
    const float* obv = (const float*)d_in[17];
    float* outp = (float*)d_out;

    float *px0, *penh, *poff, *pc1, *pc2;
    __nv_bfloat16 *puh, *pul, *pw1h, *pw1l, *pw2h, *pw2l;
    __nv_bfloat16 *pfah, *pfal, *ppwh, *ppwl;
    cudaGetSymbolAddress((void**)&px0,  g_x0t);
    cudaGetSymbolAddress((void**)&penh, g_enht);
    cudaGetSymbolAddress((void**)&poff, g_off);
    cudaGetSymbolAddress((void**)&puh,  g_uph);
    cudaGetSymbolAddress((void**)&pul,  g_upl);
    cudaGetSymbolAddress((void**)&pc1,  g_c1t);
    cudaGetSymbolAddress((void**)&pc2,  g_c2t);
    cudaGetSymbolAddress((void**)&pw1h, g_w1h);
    cudaGetSymbolAddress((void**)&pw1l, g_w1l);
    cudaGetSymbolAddress((void**)&pw2h, g_w2h);
    cudaGetSymbolAddress((void**)&pw2l, g_w2l);
    cudaGetSymbolAddress((void**)&pfah, g_fah);
    cudaGetSymbolAddress((void**)&pfal, g_fal);
    cudaGetSymbolAddress((void**)&ppwh, g_pwh);
    cudaGetSymbolAddress((void**)&ppwl, g_pwl);

    cudaFuncSetAttribute(conv_mma,   cudaFuncAttributeMaxDynamicSharedMemorySize, CONV_SMEM);
    cudaFuncSetAttribute(fusion_mma, cudaFuncAttributeMaxDynamicSharedMemorySize, FUS_SMEM);

    // 0) pre-split conv weights + fusion operands (transpose to token/f-major)
    wconv_kernel<<<2304, 256>>>(cw1, pw1h, pw1l);
    wconv_kernel<<<2304, 256>>>(cw2, pw2h, pw2l);
    const float* fs[4] = {f1, f2, f3, f4};
    for (int l = 0; l < 4; l++)
        tsplit_kernel<<<dim3(32, 24, 4), 256>>>(fs[l],
            pfah + (size_t)l*BN*N0*CIN, pfal + (size_t)l*BN*N0*CIN, CIN, N0);
    tsplit_kernel<<<dim3(8, 24, 4), 256>>>(pw, ppwh, ppwl, CIN, FC);
    // 1) weighted fusion via warp-MMA -> HWC (B,32,32,256)
    fusion_mma<<<dim3(64, 2), 256, FUS_SMEM>>>(pfah, pfal, ppwh, ppwl, lw, px0);
    // 2) depthwise enhancer (HWC)
    enhance_kernel<<<4096, 256>>>(px0, dww, bne, penh);
    // 3) stage 1: offsets, upsample to 64x64 (bf16 hi/lo), warp-MMA conv
    offset_kernel  <<<512,  256>>>(penh, ow1, ob1, poff, 32, 32);
    upsample_kernel<<<4096, 256>>>(penh, poff, puh, pul, 32, 32);
    conv_mma<<<dim3(128, 2), 256, CONV_SMEM>>>(puh, pul, pw1h, pw1l, bn1, pc1, 64, 64);
    // 4) stage 2: offsets, upsample to 128x128, warp-MMA conv
    offset_kernel  <<<2048,  256>>>(pc1, ow2, ob2, poff, 64, 64);
    upsample_kernel<<<16384, 256>>>(pc1, poff, puh, pul, 64, 64);
    conv_mma<<<dim3(512, 2), 256, CONV_SMEM>>>(puh, pul, pw2h, pw2l, bn2, pc2, 128, 128);
    // 5) depth head (HWC reduction)
    outconv_kernel <<<256, 256>>>(pc2, owv, obv, outp, 128, 128);
}